// round 10
// baseline (speedup 1.0000x reference)
#include <cuda_runtime.h>

#define NN 100000
#define F1 128
#define HEADS 4
#define OC 32
#define NEG 0.2f
#define MAXE 1700000

// ---------------- scratch (static device globals) ----------------
__device__ __align__(16) float g_h1[NN * F1];
__device__ __align__(16) float g_out1[NN * F1];
__device__ __align__(16) float g_as1[NN * HEADS];
__device__ __align__(16) float g_ad1[NN * HEADS];
__device__ __align__(16) float g_h2[NN * OC];
__device__ __align__(16) float g_as2[NN];
__device__ __align__(16) float g_ad2[NN];
__device__ int g_deg[NN];
__device__ int g_off[NN + 1];
__device__ int g_cursor[NN];
__device__ int g_bsum[1024];
__device__ int g_csr[MAXE];
// fragment-ordered, tf32-split weights: {b0_hi, b1_hi, b0_lo, b1_lo}
__device__ uint4 g_wf1[16 * 16 * 32];   // [kstep][ntile][lane]
__device__ uint4 g_wf2[16 * 4 * 32];

__device__ __forceinline__ float lrelu(float x) { return x > 0.f ? x : NEG * x; }

__device__ __forceinline__ unsigned tf32hi(float x) {
    unsigned r;
    asm("cvt.rna.tf32.f32 %0, %1;" : "=r"(r) : "f"(x));
    return r;
}

__device__ __forceinline__ void mma8(float* c, const unsigned* a, unsigned b0, unsigned b1) {
    asm volatile("mma.sync.aligned.m16n8k8.row.col.f32.tf32.tf32.f32 "
                 "{%0,%1,%2,%3}, {%4,%5,%6,%7}, {%8,%9}, {%0,%1,%2,%3};"
                 : "+f"(c[0]), "+f"(c[1]), "+f"(c[2]), "+f"(c[3])
                 : "r"(a[0]), "r"(a[1]), "r"(a[2]), "r"(a[3]), "r"(b0), "r"(b1));
}

// ---------------- weight prep: split + fragment order ----------------
__global__ void wprep(const float* __restrict__ W1, const float* __restrict__ W2) {
    int i = blockIdx.x * blockDim.x + threadIdx.x;
    if (i < 16 * 16 * 32) {
        int lane = i & 31, nt = (i >> 5) & 15, ks = i >> 9;
        int t4 = lane & 3, gid = lane >> 2;
        int k0 = ks * 8 + t4, nc = nt * 8 + gid;
        float b0 = W1[k0 * 128 + nc];
        float b1 = W1[(k0 + 4) * 128 + nc];
        unsigned h0 = tf32hi(b0), h1 = tf32hi(b1);
        unsigned l0 = tf32hi(b0 - __uint_as_float(h0));
        unsigned l1 = tf32hi(b1 - __uint_as_float(h1));
        g_wf1[i] = make_uint4(h0, h1, l0, l1);
    }
    if (i < 16 * 4 * 32) {
        int lane = i & 31, nt = (i >> 5) & 3, ks = i >> 7;
        int t4 = lane & 3, gid = lane >> 2;
        int k0 = ks * 8 + t4, nc = nt * 8 + gid;
        float b0 = W2[k0 * 32 + nc];
        float b1 = W2[(k0 + 4) * 32 + nc];
        unsigned h0 = tf32hi(b0), h1 = tf32hi(b1);
        unsigned l0 = tf32hi(b0 - __uint_as_float(h0));
        unsigned l1 = tf32hi(b1 - __uint_as_float(h1));
        g_wf2[i] = make_uint4(h0, h1, l0, l1);
    }
}

// ---------------- CSR build ----------------
__global__ void zero_deg(int n) {
    int i = blockIdx.x * blockDim.x + threadIdx.x;
    if (i < n) g_deg[i] = 0;
}

__global__ void hist_kernel(const int* __restrict__ dst, int e) {
    int i = blockIdx.x * blockDim.x + threadIdx.x;
    if (i < e) atomicAdd(&g_deg[dst[i]], 1);
}

__global__ void scan_block(int n) {
    __shared__ int sh[2][256];
    int t = threadIdx.x;
    int i = blockIdx.x * 256 + t;
    int val = (i < n) ? g_deg[i] : 0;
    int cur = 0;
    sh[0][t] = val;
    __syncthreads();
#pragma unroll
    for (int o = 1; o < 256; o <<= 1) {
        int v = sh[cur][t];
        if (t >= o) v += sh[cur][t - o];
        sh[cur ^ 1][t] = v;
        cur ^= 1;
        __syncthreads();
    }
    int incl = sh[cur][t];
    if (i < n) g_off[i] = incl - val;
    if (t == 255) g_bsum[blockIdx.x] = incl;
}

__global__ void scan_top(int nb) {
    __shared__ int sh[2][1024];
    int t = threadIdx.x;
    int val = (t < nb) ? g_bsum[t] : 0;
    int cur = 0;
    sh[0][t] = val;
    __syncthreads();
#pragma unroll
    for (int o = 1; o < 1024; o <<= 1) {
        int v = sh[cur][t];
        if (t >= o) v += sh[cur][t - o];
        sh[cur ^ 1][t] = v;
        cur ^= 1;
        __syncthreads();
    }
    if (t < nb) g_bsum[t] = sh[cur][t] - val;
}

__global__ void scan_add(int n, int e) {
    int i = blockIdx.x * blockDim.x + threadIdx.x;
    if (i < n) {
        int off = g_off[i] + g_bsum[i >> 8];
        g_off[i] = off;
        g_cursor[i] = off;
    }
    if (i == 0) g_off[n] = e;
}

__global__ void fill_kernel(const int* __restrict__ src, const int* __restrict__ dst, int e) {
    int i = blockIdx.x * blockDim.x + threadIdx.x;
    if (i >= e) return;
    int pos = atomicAdd(&g_cursor[dst[i]], 1);
    g_csr[pos] = src[i];
}

// ---------------- GEMM1 (tensor, tf32 split) + fused att1 ----------------
// block: 128 rows, 8 warps; warp w: rows w*16 + {gid, gid+8}, all 128 cols
__global__ void gemm1t(const float* __restrict__ x,
                       const float* __restrict__ asf, const float* __restrict__ adf, int n) {
    extern __shared__ uint4 wfs[];   // 8192 entries = 128 KB
    for (int i = threadIdx.x; i < 8192; i += 256) wfs[i] = g_wf1[i];
    __syncthreads();

    int warp = threadIdx.x >> 5, lane = threadIdx.x & 31;
    int t4 = lane & 3, gid = lane >> 2;
    int r0 = blockIdx.x * 128 + warp * 16 + gid;
    int r1 = r0 + 8;
    bool v0 = r0 < n, v1 = r1 < n;
    const float* xr0 = x + (long long)r0 * 128;
    const float* xr1 = x + (long long)r1 * 128;

    float acc[16][4];
#pragma unroll
    for (int nt = 0; nt < 16; nt++)
#pragma unroll
        for (int q = 0; q < 4; q++) acc[nt][q] = 0.f;

    float a[4];
    a[0] = v0 ? xr0[t4] : 0.f;
    a[1] = v1 ? xr1[t4] : 0.f;
    a[2] = v0 ? xr0[t4 + 4] : 0.f;
    a[3] = v1 ? xr1[t4 + 4] : 0.f;

#pragma unroll
    for (int ks = 0; ks < 16; ks++) {
        unsigned ahi[4], alo[4];
#pragma unroll
        for (int q = 0; q < 4; q++) {
            ahi[q] = tf32hi(a[q]);
            alo[q] = tf32hi(a[q] - __uint_as_float(ahi[q]));
        }
        if (ks < 15) {
            int kb = (ks + 1) * 8;
            a[0] = v0 ? xr0[kb + t4] : 0.f;
            a[1] = v1 ? xr1[kb + t4] : 0.f;
            a[2] = v0 ? xr0[kb + t4 + 4] : 0.f;
            a[3] = v1 ? xr1[kb + t4 + 4] : 0.f;
        }
        const uint4* bp = wfs + ks * 512 + lane;
#pragma unroll
        for (int nt = 0; nt < 16; nt++) {
            uint4 b = bp[nt * 32];
            mma8(acc[nt], ahi, b.x, b.y);   // hi*hi
            mma8(acc[nt], ahi, b.z, b.w);   // hi*lo
            mma8(acc[nt], alo, b.x, b.y);   // lo*hi
        }
    }

    // store h1
#pragma unroll
    for (int nt = 0; nt < 16; nt++) {
        int c = nt * 8 + 2 * t4;
        if (v0) *(float2*)&g_h1[(long long)r0 * 128 + c] = make_float2(acc[nt][0], acc[nt][1]);
        if (v1) *(float2*)&g_h1[(long long)r1 * 128 + c] = make_float2(acc[nt][2], acc[nt][3]);
    }

    // fused att1: per head, dot over 32 cols, quad reduce
#pragma unroll
    for (int h = 0; h < 4; h++) {
        float s0 = 0.f, d0 = 0.f, s1 = 0.f, d1 = 0.f;
#pragma unroll
        for (int q = 0; q < 4; q++) {
            int nt = h * 4 + q;
            int c = nt * 8 + 2 * t4;
            float a0 = __ldg(&asf[c]), a1 = __ldg(&asf[c + 1]);
            float e0 = __ldg(&adf[c]), e1 = __ldg(&adf[c + 1]);
            s0 += acc[nt][0] * a0 + acc[nt][1] * a1;
            d0 += acc[nt][0] * e0 + acc[nt][1] * e1;
            s1 += acc[nt][2] * a0 + acc[nt][3] * a1;
            d1 += acc[nt][2] * e0 + acc[nt][3] * e1;
        }
        s0 += __shfl_xor_sync(0xffffffffu, s0, 1); s0 += __shfl_xor_sync(0xffffffffu, s0, 2);
        d0 += __shfl_xor_sync(0xffffffffu, d0, 1); d0 += __shfl_xor_sync(0xffffffffu, d0, 2);
        s1 += __shfl_xor_sync(0xffffffffu, s1, 1); s1 += __shfl_xor_sync(0xffffffffu, s1, 2);
        d1 += __shfl_xor_sync(0xffffffffu, d1, 1); d1 += __shfl_xor_sync(0xffffffffu, d1, 2);
        if (t4 == 0) {
            if (v0) { g_as1[r0 * 4 + h] = s0; g_ad1[r0 * 4 + h] = d0; }
            if (v1) { g_as1[r1 * 4 + h] = s1; g_ad1[r1 * 4 + h] = d1; }
        }
    }
}

// ---------------- layer1 aggregation: one warp per dst node ----------------
__global__ void agg1_kernel(const float* __restrict__ b1, int n) {
    int w = (blockIdx.x * blockDim.x + threadIdx.x) >> 5;
    int lane = threadIdx.x & 31;
    if (w >= n) return;
    int rs = g_off[w], re = g_off[w + 1];
    int h = lane >> 3;
    float4 ad4 = ((const float4*)g_ad1)[w];
    float adh = (h == 0) ? ad4.x : (h == 1) ? ad4.y : (h == 2) ? ad4.z : ad4.w;

    float4 den = make_float4(0.f, 0.f, 0.f, 0.f);
    for (int j = rs + lane; j < re; j += 32) {
        int s = __ldg(&g_csr[j]);
        float4 as = ((const float4*)g_as1)[s];
        den.x += __expf(lrelu(as.x + ad4.x));
        den.y += __expf(lrelu(as.y + ad4.y));
        den.z += __expf(lrelu(as.z + ad4.z));
        den.w += __expf(lrelu(as.w + ad4.w));
    }
#pragma unroll
    for (int o = 16; o; o >>= 1) {
        den.x += __shfl_xor_sync(0xffffffffu, den.x, o);
        den.y += __shfl_xor_sync(0xffffffffu, den.y, o);
        den.z += __shfl_xor_sync(0xffffffffu, den.z, o);
        den.w += __shfl_xor_sync(0xffffffffu, den.w, o);
    }
    float4 as_self = ((const float4*)g_as1)[w];
    den.x += __expf(lrelu(as_self.x + ad4.x));
    den.y += __expf(lrelu(as_self.y + ad4.y));
    den.z += __expf(lrelu(as_self.z + ad4.z));
    den.w += __expf(lrelu(as_self.w + ad4.w));
    float denh = (h == 0) ? den.x : (h == 1) ? den.y : (h == 2) ? den.z : den.w;
    float invh = 1.f / denh;
    float ash = (h == 0) ? as_self.x : (h == 1) ? as_self.y : (h == 2) ? as_self.z : as_self.w;
    float wself = __expf(lrelu(ash + adh)) * invh;

    float4 acc = make_float4(0.f, 0.f, 0.f, 0.f);
    int j = rs;
    for (; j + 1 < re; j += 2) {
        int s0 = __ldg(&g_csr[j]), s1 = __ldg(&g_csr[j + 1]);
        float a0 = g_as1[s0 * 4 + h], a1 = g_as1[s1 * 4 + h];
        float4 hv0 = *(const float4*)(g_h1 + (long long)s0 * 128 + lane * 4);
        float4 hv1 = *(const float4*)(g_h1 + (long long)s1 * 128 + lane * 4);
        float w0 = __expf(lrelu(a0 + adh)) * invh;
        float w1 = __expf(lrelu(a1 + adh)) * invh;
        acc.x += hv0.x * w0 + hv1.x * w1;
        acc.y += hv0.y * w0 + hv1.y * w1;
        acc.z += hv0.z * w0 + hv1.z * w1;
        acc.w += hv0.w * w0 + hv1.w * w1;
    }
    if (j < re) {
        int s = __ldg(&g_csr[j]);
        float a = g_as1[s * 4 + h];
        float ww = __expf(lrelu(a + adh)) * invh;
        float4 hv = *(const float4*)(g_h1 + (long long)s * 128 + lane * 4);
        acc.x += hv.x * ww; acc.y += hv.y * ww; acc.z += hv.z * ww; acc.w += hv.w * ww;
    }
    float4 hs = *(const float4*)(g_h1 + (long long)w * 128 + lane * 4);
    float4 bb = ((const float4*)b1)[lane];
    acc.x += hs.x * wself + bb.x;
    acc.y += hs.y * wself + bb.y;
    acc.z += hs.z * wself + bb.z;
    acc.w += hs.w * wself + bb.w;
    acc.x = acc.x > 0.f ? acc.x : (__expf(acc.x) - 1.f);
    acc.y = acc.y > 0.f ? acc.y : (__expf(acc.y) - 1.f);
    acc.z = acc.z > 0.f ? acc.z : (__expf(acc.z) - 1.f);
    acc.w = acc.w > 0.f ? acc.w : (__expf(acc.w) - 1.f);
    *(float4*)(g_out1 + (long long)w * 128 + lane * 4) = acc;
}

// ---------------- GEMM2 (tensor, tf32 split) + fused att2 ----------------
__global__ void gemm2t(const float* __restrict__ asf, const float* __restrict__ adf, int n) {
    __shared__ uint4 wfs[2048];   // 32 KB
    for (int i = threadIdx.x; i < 2048; i += 256) wfs[i] = g_wf2[i];
    __syncthreads();

    int warp = threadIdx.x >> 5, lane = threadIdx.x & 31;
    int t4 = lane & 3, gid = lane >> 2;
    int r0 = blockIdx.x * 128 + warp * 16 + gid;
    int r1 = r0 + 8;
    bool v0 = r0 < n, v1 = r1 < n;
    const float* xr0 = g_out1 + (long long)r0 * 128;
    const float* xr1 = g_out1 + (long long)r1 * 128;

    float acc[4][4];
#pragma unroll
    for (int nt = 0; nt < 4; nt++)
#pragma unroll
        for (int q = 0; q < 4; q++) acc[nt][q] = 0.f;

    float a[4];
    a[0] = v0 ? xr0[t4] : 0.f;
    a[1] = v1 ? xr1[t4] : 0.f;
    a[2] = v0 ? xr0[t4 + 4] : 0.f;
    a[3] = v1 ? xr1[t4 + 4] : 0.f;

#pragma unroll
    for (int ks = 0; ks < 16; ks++) {
        unsigned ahi[4], alo[4];
#pragma unroll
        for (int q = 0; q < 4; q++) {
            ahi[q] = tf32hi(a[q]);
            alo[q] = tf32hi(a[q] - __uint_as_float(ahi[q]));
        }
        if (ks < 15) {
            int kb = (ks + 1) * 8;
            a[0] = v0 ? xr0[kb + t4] : 0.f;
            a[1] = v1 ? xr1[kb + t4] : 0.f;
            a[2] = v0 ? xr0[kb + t4 + 4] : 0.f;
            a[3] = v1 ? xr1[kb + t4 + 4] : 0.f;
        }
        const uint4* bp = wfs + ks * 128 + lane;
#pragma unroll
        for (int nt = 0; nt < 4; nt++) {
            uint4 b = bp[nt * 32];
            mma8(acc[nt], ahi, b.x, b.y);
            mma8(acc[nt], ahi, b.z, b.w);
            mma8(acc[nt], alo, b.x, b.y);
        }
    }

#pragma unroll
    for (int nt = 0; nt < 4; nt++) {
        int c = nt * 8 + 2 * t4;
        if (v0) *(float2*)&g_h2[(long long)r0 * 32 + c] = make_float2(acc[nt][0], acc[nt][1]);
        if (v1) *(float2*)&g_h2[(long long)r1 * 32 + c] = make_float2(acc[nt][2], acc[nt][3]);
    }

    float s0 = 0.f, d0 = 0.f, s1 = 0.f, d1 = 0.f;
#pragma unroll
    for (int nt = 0; nt < 4; nt++) {
        int c = nt * 8 + 2 * t4;
        float a0 = __ldg(&asf[c]), a1 = __ldg(&asf[c + 1]);
        float e0 = __ldg(&adf[c]), e1 = __ldg(&adf[c + 1]);
        s0 += acc[nt][0] * a0 + acc[nt][1] * a1;
        d0 += acc[nt][0] * e0 + acc[nt][1] * e1;
        s1 += acc[nt][2] * a0 + acc[nt][3] * a1;
        d1 += acc[nt][2] * e0 + acc[nt][3] * e1;
    }
    s0 += __shfl_xor_sync(0xffffffffu, s0, 1); s0 += __shfl_xor_sync(0xffffffffu, s0, 2);
    d0 += __shfl_xor_sync(0xffffffffu, d0, 1); d0 += __shfl_xor_sync(0xffffffffu, d0, 2);
    s1 += __shfl_xor_sync(0xffffffffu, s1, 1); s1 += __shfl_xor_sync(0xffffffffu, s1, 2);
    d1 += __shfl_xor_sync(0xffffffffu, d1, 1); d1 += __shfl_xor_sync(0xffffffffu, d1, 2);
    if (t4 == 0) {
        if (v0) { g_as2[r0] = s0; g_ad2[r0] = d0; }
        if (v1) { g_as2[r1] = s1; g_ad2[r1] = d1; }
    }
}

// ---------------- layer2 aggregation + log_softmax: one warp per dst ----------------
__global__ void agg2_kernel(const float* __restrict__ b2, float* __restrict__ out, int n) {
    int w = (blockIdx.x * blockDim.x + threadIdx.x) >> 5;
    int lane = threadIdx.x & 31;
    if (w >= n) return;
    int rs = g_off[w], re = g_off[w + 1];
    float ad = g_ad2[w];

    float den = 0.f;
    for (int j = rs + lane; j < re; j += 32) {
        int s = __ldg(&g_csr[j]);
        den += __expf(lrelu(g_as2[s] + ad));
    }
#pragma unroll
    for (int o = 16; o; o >>= 1) den += __shfl_xor_sync(0xffffffffu, den, o);
    float as_self = g_as2[w];
    den += __expf(lrelu(as_self + ad));
    float inv = 1.f / den;
    float wself = __expf(lrelu(as_self + ad)) * inv;

    float acc = 0.f;
    int j = rs;
    for (; j + 1 < re; j += 2) {
        int s0 = __ldg(&g_csr[j]), s1 = __ldg(&g_csr[j + 1]);
        float w0 = __expf(lrelu(g_as2[s0] + ad)) * inv;
        float w1 = __expf(lrelu(g_as2[s1] + ad)) * inv;
        acc += g_h2[s0 * 32 + lane] * w0 + g_h2[s1 * 32 + lane] * w1;
    }
    if (j < re) {
        int s = __ldg(&g_csr[j]);
        float ww = __expf(lrelu(g_as2[s] + ad)) * inv;
        acc += g_h2[s * 32 + lane] * ww;
    }
    acc += g_h2[w * 32 + lane] * wself + b2[lane];

    float mx = acc;
#pragma unroll
    for (int o = 16; o; o >>= 1) mx = fmaxf(mx, __shfl_xor_sync(0xffffffffu, mx, o));
    float ex = __expf(acc - mx);
    float ssum = ex;
#pragma unroll
    for (int o = 16; o; o >>= 1) ssum += __shfl_xor_sync(0xffffffffu, ssum, o);
    out[(long long)w * 32 + lane] = acc - mx - logf(ssum);
}

extern "C" void kernel_launch(void* const* d_in, const int* in_sizes, int n_in,
                              void* d_out, int out_size) {
    const float* x     = (const float*)d_in[0];
    const int*   ei    = (const int*)d_in[1];
    const float* W1    = (const float*)d_in[2];
    const float* at_s1 = (const float*)d_in[3];
    const float* at_d1 = (const float*)d_in[4];
    const float* b1    = (const float*)d_in[5];
    const float* W2    = (const float*)d_in[6];
    const float* at_s2 = (const float*)d_in[7];
    const float* at_d2 = (const float*)d_in[8];
    const float* b2    = (const float*)d_in[9];
    float* out = (float*)d_out;

    int n = in_sizes[0] / 128;
    int e = in_sizes[1] / 2;
    const int* src = ei;
    const int* dst = ei + e;
    int nb = (n + 255) / 256;

    cudaFuncSetAttribute(gemm1t, cudaFuncAttributeMaxDynamicSharedMemorySize, 131072);

    wprep<<<32, 256>>>(W1, W2);

    zero_deg<<<nb, 256>>>(n);
    hist_kernel<<<(e + 255) / 256, 256>>>(dst, e);
    scan_block<<<nb, 256>>>(n);
    scan_top<<<1, 1024>>>(nb);
    scan_add<<<nb, 256>>>(n, e);
    fill_kernel<<<(e + 255) / 256, 256>>>(src, dst, e);

    gemm1t<<<(n + 127) / 128, 256, 131072>>>(x, at_s1, at_d1, n);
    agg1_kernel<<<(n + 7) / 8, 256>>>(b1, n);

    gemm2t<<<(n + 127) / 128, 256>>>(at_s2, at_d2, n);
    agg2_kernel<<<(n + 7) / 8, 256>>>(b2, out, n);
}

// round 13
// speedup vs baseline: 1.2816x; 1.2816x over previous
#include <cuda_runtime.h>
#include <cstdint>

#define NN 100000
#define F1 128
#define HEADS 4
#define OC 32
#define NEG 0.2f
#define MAXE 1700000

// ---------------- scratch (static device globals) ----------------
__device__ __align__(16) float g_h1[NN * F1];
__device__ __align__(16) float g_out1[NN * F1];
__device__ __align__(16) float g_as1[NN * HEADS];
__device__ __align__(16) float g_ad1[NN * HEADS];
__device__ __align__(16) float g_h2[NN * OC];
__device__ __align__(16) float g_as2[NN];
__device__ __align__(16) float g_ad2[NN];
__device__ int g_deg[NN];
__device__ int g_off[NN + 1];
__device__ int g_cursor[NN];
__device__ int g_bsum[1024];
__device__ int g_csr[MAXE];

__device__ __forceinline__ float lrelu(float x) { return x > 0.f ? x : NEG * x; }

// ---- packed fp32 FMA (Blackwell f32x2; double-rate, full fp32 precision) ----
__device__ __forceinline__ void ffma2(unsigned long long& acc, unsigned long long a, unsigned long long b) {
    asm("fma.rn.f32x2 %0, %1, %2, %3;" : "=l"(acc) : "l"(a), "l"(b), "l"(acc));
}
__device__ __forceinline__ unsigned long long packf2(float lo, float hi) {
    unsigned long long r;
    asm("mov.b64 %0, {%1, %2};" : "=l"(r) : "f"(lo), "f"(hi));
    return r;
}
__device__ __forceinline__ float2 unpackf2(unsigned long long v) {
    float2 r;
    asm("mov.b64 {%0, %1}, %2;" : "=f"(r.x), "=f"(r.y) : "l"(v));
    return r;
}

// ---------------- CSR build ----------------
__global__ void zero_deg(int n) {
    int i = blockIdx.x * blockDim.x + threadIdx.x;
    if (i < n) g_deg[i] = 0;
}
__global__ void hist_kernel(const int* __restrict__ dst, int e) {
    int i = blockIdx.x * blockDim.x + threadIdx.x;
    if (i < e) atomicAdd(&g_deg[dst[i]], 1);
}
__global__ void scan_block(int n) {
    __shared__ int sh[2][256];
    int t = threadIdx.x;
    int i = blockIdx.x * 256 + t;
    int val = (i < n) ? g_deg[i] : 0;
    int cur = 0;
    sh[0][t] = val;
    __syncthreads();
#pragma unroll
    for (int o = 1; o < 256; o <<= 1) {
        int v = sh[cur][t];
        if (t >= o) v += sh[cur][t - o];
        sh[cur ^ 1][t] = v;
        cur ^= 1;
        __syncthreads();
    }
    int incl = sh[cur][t];
    if (i < n) g_off[i] = incl - val;
    if (t == 255) g_bsum[blockIdx.x] = incl;
}
__global__ void scan_top(int nb) {
    __shared__ int sh[2][1024];
    int t = threadIdx.x;
    int val = (t < nb) ? g_bsum[t] : 0;
    int cur = 0;
    sh[0][t] = val;
    __syncthreads();
#pragma unroll
    for (int o = 1; o < 1024; o <<= 1) {
        int v = sh[cur][t];
        if (t >= o) v += sh[cur][t - o];
        sh[cur ^ 1][t] = v;
        cur ^= 1;
        __syncthreads();
    }
    if (t < nb) g_bsum[t] = sh[cur][t] - val;
}
__global__ void scan_add(int n, int e) {
    int i = blockIdx.x * blockDim.x + threadIdx.x;
    if (i < n) {
        int off = g_off[i] + g_bsum[i >> 8];
        g_off[i] = off;
        g_cursor[i] = off;
    }
    if (i == 0) g_off[n] = e;
}
__global__ void fill_kernel(const int* __restrict__ src, const int* __restrict__ dst, int e) {
    int i = blockIdx.x * blockDim.x + threadIdx.x;
    if (i >= e) return;
    int pos = atomicAdd(&g_cursor[dst[i]], 1);
    g_csr[pos] = src[i];
}

// ---------------- GEMM1: h1[N,128] = x[N,128] @ W1[128,128] (f32x2) ----------------
__global__ void gemm1_kernel(const float* __restrict__ x, const float* __restrict__ W, int n) {
    __shared__ float xs[64][68];  // [k][row], padded
    __shared__ float ws[64][64];  // [k][col]
    int tid = threadIdx.x;
    int tx = tid & 15, ty = tid >> 4;
    int row0 = blockIdx.x * 64, col0 = blockIdx.y * 64;
    unsigned long long acc2[4][2];
#pragma unroll
    for (int i = 0; i < 4; i++) { acc2[i][0] = 0ull; acc2[i][1] = 0ull; }
    for (int kt = 0; kt < 2; kt++) {
        int kb = kt * 64;
        for (int i = tid; i < 4096; i += 256) {
            int r = i >> 6, k = i & 63;
            int gr = row0 + r;
            xs[k][r] = (gr < n) ? x[gr * 128 + kb + k] : 0.f;
        }
        for (int i = tid; i < 4096; i += 256) {
            int k = i >> 6, c = i & 63;
            ws[k][c] = W[(kb + k) * 128 + col0 + c];
        }
        __syncthreads();
#pragma unroll 8
        for (int k = 0; k < 64; k++) {
            float4 a = *(const float4*)&xs[k][ty * 4];
            unsigned long long b01 = *(const unsigned long long*)&ws[k][tx * 4];
            unsigned long long b23 = *(const unsigned long long*)&ws[k][tx * 4 + 2];
            unsigned long long ad;
            ad = packf2(a.x, a.x); ffma2(acc2[0][0], ad, b01); ffma2(acc2[0][1], ad, b23);
            ad = packf2(a.y, a.y); ffma2(acc2[1][0], ad, b01); ffma2(acc2[1][1], ad, b23);
            ad = packf2(a.z, a.z); ffma2(acc2[2][0], ad, b01); ffma2(acc2[2][1], ad, b23);
            ad = packf2(a.w, a.w); ffma2(acc2[3][0], ad, b01); ffma2(acc2[3][1], ad, b23);
        }
        __syncthreads();
    }
#pragma unroll
    for (int ii = 0; ii < 4; ii++) {
        int gr = row0 + ty * 4 + ii;
        if (gr < n) {
            float2 lo = unpackf2(acc2[ii][0]);
            float2 hi = unpackf2(acc2[ii][1]);
            *(float4*)&g_h1[gr * 128 + col0 + tx * 4] = make_float4(lo.x, lo.y, hi.x, hi.y);
        }
    }
}

// ---------------- attention logits layer 1 ----------------
__global__ void att1_kernel(const float4* __restrict__ asr, const float4* __restrict__ adr, int n) {
    int i = blockIdx.x * blockDim.x + threadIdx.x;
    if (i >= n) return;
    const float4* hp = (const float4*)(g_h1 + (long long)i * 128);
#pragma unroll
    for (int h = 0; h < 4; h++) {
        float s = 0.f, d = 0.f;
#pragma unroll
        for (int j = 0; j < 8; j++) {
            float4 v = hp[h * 8 + j];
            float4 a = asr[h * 8 + j];
            float4 b = adr[h * 8 + j];
            s += v.x * a.x + v.y * a.y + v.z * a.z + v.w * a.w;
            d += v.x * b.x + v.y * b.y + v.z * b.z + v.w * b.w;
        }
        g_as1[i * 4 + h] = s;
        g_ad1[i * 4 + h] = d;
    }
}

// ---------------- layer1 aggregation: one warp per dst node ----------------
__global__ void agg1_kernel(const float* __restrict__ b1, int n) {
    int w = (blockIdx.x * blockDim.x + threadIdx.x) >> 5;
    int lane = threadIdx.x & 31;
    if (w >= n) return;
    int rs = g_off[w], re = g_off[w + 1];
    int h = lane >> 3;
    float4 ad4 = ((const float4*)g_ad1)[w];
    float adh = (h == 0) ? ad4.x : (h == 1) ? ad4.y : (h == 2) ? ad4.z : ad4.w;

    float4 den = make_float4(0.f, 0.f, 0.f, 0.f);
    for (int j = rs + lane; j < re; j += 32) {
        int s = __ldg(&g_csr[j]);
        float4 as = ((const float4*)g_as1)[s];
        den.x += __expf(lrelu(as.x + ad4.x));
        den.y += __expf(lrelu(as.y + ad4.y));
        den.z += __expf(lrelu(as.z + ad4.z));
        den.w += __expf(lrelu(as.w + ad4.w));
    }
#pragma unroll
    for (int o = 16; o; o >>= 1) {
        den.x += __shfl_xor_sync(0xffffffffu, den.x, o);
        den.y += __shfl_xor_sync(0xffffffffu, den.y, o);
        den.z += __shfl_xor_sync(0xffffffffu, den.z, o);
        den.w += __shfl_xor_sync(0xffffffffu, den.w, o);
    }
    float4 as_self = ((const float4*)g_as1)[w];
    den.x += __expf(lrelu(as_self.x + ad4.x));
    den.y += __expf(lrelu(as_self.y + ad4.y));
    den.z += __expf(lrelu(as_self.z + ad4.z));
    den.w += __expf(lrelu(as_self.w + ad4.w));
    float denh = (h == 0) ? den.x : (h == 1) ? den.y : (h == 2) ? den.z : den.w;
    float invh = 1.f / denh;
    float ash = (h == 0) ? as_self.x : (h == 1) ? as_self.y : (h == 2) ? as_self.z : as_self.w;
    float wself = __expf(lrelu(ash + adh)) * invh;

    float4 acc = make_float4(0.f, 0.f, 0.f, 0.f);
    int j = rs;
    for (; j + 1 < re; j += 2) {
        int s0 = __ldg(&g_csr[j]), s1 = __ldg(&g_csr[j + 1]);
        float a0 = g_as1[s0 * 4 + h], a1 = g_as1[s1 * 4 + h];
        float4 hv0 = *(const float4*)(g_h1 + (long long)s0 * 128 + lane * 4);
        float4 hv1 = *(const float4*)(g_h1 + (long long)s1 * 128 + lane * 4);
        float w0 = __expf(lrelu(a0 + adh)) * invh;
        float w1 = __expf(lrelu(a1 + adh)) * invh;
        acc.x += hv0.x * w0 + hv1.x * w1;
        acc.y += hv0.y * w0 + hv1.y * w1;
        acc.z += hv0.z * w0 + hv1.z * w1;
        acc.w += hv0.w * w0 + hv1.w * w1;
    }
    if (j < re) {
        int s = __ldg(&g_csr[j]);
        float a = g_as1[s * 4 + h];
        float ww = __expf(lrelu(a + adh)) * invh;
        float4 hv = *(const float4*)(g_h1 + (long long)s * 128 + lane * 4);
        acc.x += hv.x * ww; acc.y += hv.y * ww; acc.z += hv.z * ww; acc.w += hv.w * ww;
    }
    float4 hs = *(const float4*)(g_h1 + (long long)w * 128 + lane * 4);
    float4 bb = ((const float4*)b1)[lane];
    acc.x += hs.x * wself + bb.x;
    acc.y += hs.y * wself + bb.y;
    acc.z += hs.z * wself + bb.z;
    acc.w += hs.w * wself + bb.w;
    acc.x = acc.x > 0.f ? acc.x : (__expf(acc.x) - 1.f);
    acc.y = acc.y > 0.f ? acc.y : (__expf(acc.y) - 1.f);
    acc.z = acc.z > 0.f ? acc.z : (__expf(acc.z) - 1.f);
    acc.w = acc.w > 0.f ? acc.w : (__expf(acc.w) - 1.f);
    *(float4*)(g_out1 + (long long)w * 128 + lane * 4) = acc;
}

// ---------------- GEMM2: h2[N,32] = out1[N,128] @ W2[128,32] (f32x2) ----------------
__global__ void gemm2_kernel(const float* __restrict__ W, int n) {
    __shared__ float xs[64][68];
    __shared__ float ws[64][32];
    int tid = threadIdx.x;   // 128 threads
    int tx = tid & 7, ty = tid >> 3;
    int row0 = blockIdx.x * 64;
    unsigned long long acc2[4][2];
#pragma unroll
    for (int i = 0; i < 4; i++) { acc2[i][0] = 0ull; acc2[i][1] = 0ull; }
    for (int kt = 0; kt < 2; kt++) {
        int kb = kt * 64;
        for (int i = tid; i < 4096; i += 128) {
            int r = i >> 6, k = i & 63;
            int gr = row0 + r;
            xs[k][r] = (gr < n) ? g_out1[(long long)gr * 128 + kb + k] : 0.f;
        }
        for (int i = tid; i < 2048; i += 128) {
            int k = i >> 5, c = i & 31;
            ws[k][c] = W[(kb + k) * 32 + c];
        }
        __syncthreads();
#pragma unroll 8
        for (int k = 0; k < 64; k++) {
            float4 a = *(const float4*)&xs[k][ty * 4];
            unsigned long long b01 = *(const unsigned long long*)&ws[k][tx * 4];
            unsigned long long b23 = *(const unsigned long long*)&ws[k][tx * 4 + 2];
            unsigned long long ad;
            ad = packf2(a.x, a.x); ffma2(acc2[0][0], ad, b01); ffma2(acc2[0][1], ad, b23);
            ad = packf2(a.y, a.y); ffma2(acc2[1][0], ad, b01); ffma2(acc2[1][1], ad, b23);
            ad = packf2(a.z, a.z); ffma2(acc2[2][0], ad, b01); ffma2(acc2[2][1], ad, b23);
            ad = packf2(a.w, a.w); ffma2(acc2[3][0], ad, b01); ffma2(acc2[3][1], ad, b23);
        }
        __syncthreads();
    }
#pragma unroll
    for (int ii = 0; ii < 4; ii++) {
        int gr = row0 + ty * 4 + ii;
        if (gr < n) {
            float2 lo = unpackf2(acc2[ii][0]);
            float2 hi = unpackf2(acc2[ii][1]);
            *(float4*)&g_h2[gr * 32 + tx * 4] = make_float4(lo.x, lo.y, hi.x, hi.y);
        }
    }
}

// ---------------- attention logits layer 2 ----------------
__global__ void att2_kernel(const float4* __restrict__ asr, const float4* __restrict__ adr, int n) {
    int i = blockIdx.x * blockDim.x + threadIdx.x;
    if (i >= n) return;
    const float4* hp = (const float4*)(g_h2 + i * 32);
    float s = 0.f, d = 0.f;
#pragma unroll
    for (int j = 0; j < 8; j++) {
        float4 v = hp[j];
        float4 a = asr[j];
        float4 b = adr[j];
        s += v.x * a.x + v.y * a.y + v.z * a.z + v.w * a.w;
        d += v.x * b.x + v.y * b.y + v.z * b.z + v.w * b.w;
    }
    g_as2[i] = s;
    g_ad2[i] = d;
}

// ---------------- layer2 aggregation + log_softmax: one warp per dst ----------------
__global__ void agg2_kernel(const float* __restrict__ b2, float* __restrict__ out, int n) {
    int w = (blockIdx.x * blockDim.x + threadIdx.x) >> 5;
    int lane = threadIdx.x & 31;
    if (w >= n) return;
    int rs = g_off[w], re = g_off[w + 1];
    float ad = g_ad2[w];

    float den = 0.f;
    for (int j = rs + lane; j < re; j += 32) {
        int s = __ldg(&g_csr[j]);
        den += __expf(lrelu(g_as2[s] + ad));
    }
#pragma unroll
    for (int o = 16; o; o >>= 1) den += __shfl_xor_sync(0xffffffffu, den, o);
    float as_self = g_as2[w];
    den += __expf(lrelu(as_self + ad));
    float inv = 1.f / den;
    float wself = __expf(lrelu(as_self + ad)) * inv;

    float acc = 0.f;
    int j = rs;
    for (; j + 1 < re; j += 2) {
        int s0 = __ldg(&g_csr[j]), s1 = __ldg(&g_csr[j + 1]);
        float w0 = __expf(lrelu(g_as2[s0] + ad)) * inv;
        float w1 = __expf(lrelu(g_as2[s1] + ad)) * inv;
        acc += g_h2[s0 * 32 + lane] * w0 + g_h2[s1 * 32 + lane] * w1;
    }
    if (j < re) {
        int s = __ldg(&g_csr[j]);
        float ww = __expf(lrelu(g_as2[s] + ad)) * inv;
        acc += g_h2[s * 32 + lane] * ww;
    }
    acc += g_h2[w * 32 + lane] * wself + b2[lane];

    float mx = acc;
#pragma unroll
    for (int o = 16; o; o >>= 1) mx = fmaxf(mx, __shfl_xor_sync(0xffffffffu, mx, o));
    float ex = __expf(acc - mx);
    float ssum = ex;
#pragma unroll
    for (int o = 16; o; o >>= 1) ssum += __shfl_xor_sync(0xffffffffu, ssum, o);
    out[(long long)w * 32 + lane] = acc - mx - logf(ssum);
}

extern "C" void kernel_launch(void* const* d_in, const int* in_sizes, int n_in,
                              void* d_out, int out_size) {
    const float* x     = (const float*)d_in[0];
    const int*   ei    = (const int*)d_in[1];
    const float* W1    = (const float*)d_in[2];
    const float* at_s1 = (const float*)d_in[3];
    const float* at_d1 = (const float*)d_in[4];
    const float* b1    = (const float*)d_in[5];
    const float* W2    = (const float*)d_in[6];
    const float* at_s2 = (const float*)d_in[7];
    const float* at_d2 = (const float*)d_in[8];
    const float* b2    = (const float*)d_in[9];
    float* out = (float*)d_out;

    int n = in_sizes[0] / 128;
    int e = in_sizes[1] / 2;
    const int* src = ei;
    const int* dst = ei + e;
    int nb = (n + 255) / 256;

    // One-time side stream + events (handles only; no device memory).
    static cudaStream_t s1 = nullptr;
    static cudaEvent_t evF = nullptr, evJ = nullptr;
    if (s1 == nullptr) {
        cudaStreamCreate(&s1);
        cudaEventCreateWithFlags(&evF, cudaEventDisableTiming);
        cudaEventCreateWithFlags(&evJ, cudaEventDisableTiming);
    }

    // fork: CSR build on s1, GEMM1+att1 on default stream
    cudaEventRecord(evF, 0);
    cudaStreamWaitEvent(s1, evF, 0);
    zero_deg<<<nb, 256, 0, s1>>>(n);
    hist_kernel<<<(e + 255) / 256, 256, 0, s1>>>(dst, e);
    scan_block<<<nb, 256, 0, s1>>>(n);
    scan_top<<<1, 1024, 0, s1>>>(nb);
    scan_add<<<nb, 256, 0, s1>>>(n, e);
    fill_kernel<<<(e + 255) / 256, 256, 0, s1>>>(src, dst, e);
    cudaEventRecord(evJ, s1);

    dim3 g1((n + 63) / 64, 2);
    gemm1_kernel<<<g1, 256>>>(x, W1, n);
    att1_kernel<<<nb, 256>>>((const float4*)at_s1, (const float4*)at_d1, n);

    // join: aggregation needs both CSR and attention logits
    cudaStreamWaitEvent(0, evJ, 0);
    agg1_kernel<<<(n + 7) / 8, 256>>>(b1, n);

    gemm2_kernel<<<(n + 63) / 64, 128>>>(W2, n);
    att2_kernel<<<nb, 256>>>((const float4*)at_s2, (const float4*)at_d2, n);
    agg2_kernel<<<(n + 7) / 8, 256>>>(b2, out, n);
}